// round 8
// baseline (speedup 1.0000x reference)
#include <cuda_runtime.h>

typedef unsigned long long u64;

#define B_    8
#define DIM_  1024
#define T_    4096
#define CB_   4096
#define CD_   8
#define BT_   (B_*T_)
#define NSL_  16
#define SLICE_ (CB_/NSL_)   // 256

static const size_t IDX_OFF_  = (size_t)B_ * DIM_ * T_;          // 33554432
static const size_t LOSS_OFF_ = (size_t)B_ * DIM_ * T_ + BT_;    // 33587200

// ---------------- device scratch (no allocations allowed) ----------------
__device__ float g_cn[CB_ * CD_];          // normalized codebook [j][c] (128 KB, L1-resident)
__device__ float g_Win2[DIM_ * 2 * CD_];   // weight-normed in_proj, transposed+splatted [d][c][2]
__device__ float g_bin2[2 * CD_];          // b_in splatted [c][2]
__device__ float g_Wout2[DIM_ * 2 * CD_];  // weight-normed out_proj, splatted [o][c][2]
__device__ float g_bout2[DIM_ * 2];        // b_out splatted [o][2]
__device__ float g_ze[(size_t)BT_ * CD_];  // encodings z_e [t][c]  (1 MB)

// ---------------- f32x2 helpers ----------------
__device__ __forceinline__ u64 f2mul(u64 a, u64 b) {
    u64 r; asm("mul.rn.f32x2 %0, %1, %2;" : "=l"(r) : "l"(a), "l"(b)); return r;
}
__device__ __forceinline__ u64 f2fma(u64 a, u64 b, u64 c) {
    u64 r; asm("fma.rn.f32x2 %0, %1, %2, %3;" : "=l"(r) : "l"(a), "l"(b), "l"(c)); return r;
}
__device__ __forceinline__ u64 f2add(u64 a, u64 b) {
    u64 r; asm("add.rn.f32x2 %0, %1, %2;" : "=l"(r) : "l"(a), "l"(b)); return r;
}
__device__ __forceinline__ float2 f2unpack(u64 a) {
    float x, y; asm("mov.b64 {%0, %1}, %2;" : "=f"(x), "=f"(y) : "l"(a));
    return make_float2(x, y);
}

// ---------------- prep ----------------
__global__ void __launch_bounds__(256) prep_kernel(
    const float* __restrict__ v_in, const float* __restrict__ g_in,
    const float* __restrict__ b_in,
    const float* __restrict__ codebook,
    const float* __restrict__ v_out, const float* __restrict__ g_out,
    const float* __restrict__ b_out, float* __restrict__ dout)
{
    const int r = blockIdx.x * 256 + threadIdx.x;
    if (r < CB_) {
        float v[CD_]; float s = 0.f;
#pragma unroll
        for (int c = 0; c < CD_; ++c) { v[c] = codebook[(size_t)r * CD_ + c]; s += v[c] * v[c]; }
        float n = fmaxf(sqrtf(s), 1e-12f);
#pragma unroll
        for (int c = 0; c < CD_; ++c) g_cn[(size_t)r * CD_ + c] = v[c] / n;
    } else if (r < CB_ + DIM_) {
        const int o = r - CB_;
        float v[CD_]; float s = 0.f;
#pragma unroll
        for (int c = 0; c < CD_; ++c) { v[c] = v_out[(size_t)o * CD_ + c]; s += v[c] * v[c]; }
        float sc = g_out[o] / sqrtf(s);
#pragma unroll
        for (int c = 0; c < CD_; ++c) {
            float w = v[c] * sc;
            g_Wout2[o * 16 + 2 * c]     = w;
            g_Wout2[o * 16 + 2 * c + 1] = w;
        }
        float bb = b_out[o];
        g_bout2[o * 2] = bb; g_bout2[o * 2 + 1] = bb;
    } else if (r < CB_ + DIM_ + CD_ * 32) {
        // in_proj: one warp per output channel; fill transposed+splatted W_in
        const int idx  = r - (CB_ + DIM_);
        const int w    = idx >> 5;
        const int lane = idx & 31;
        float s = 0.f;
        for (int d = lane; d < DIM_; d += 32) {
            float v = v_in[(size_t)w * DIM_ + d]; s += v * v;
        }
#pragma unroll
        for (int off = 16; off > 0; off >>= 1) s += __shfl_xor_sync(0xffffffffu, s, off);
        float sc = g_in[w] / sqrtf(s);
        for (int d = lane; d < DIM_; d += 32) {
            float val = v_in[(size_t)w * DIM_ + d] * sc;
            g_Win2[d * 16 + 2 * w]     = val;
            g_Win2[d * 16 + 2 * w + 1] = val;
        }
    } else if (r < CB_ + DIM_ + CD_ * 32 + CD_) {
        const int c = r - (CB_ + DIM_ + CD_ * 32);
        float bv = b_in[c];
        g_bin2[2 * c] = bv; g_bin2[2 * c + 1] = bv;
    } else if (r < CB_ + DIM_ + CD_ * 32 + CD_ + B_) {
        dout[LOSS_OFF_ + (r - (CB_ + DIM_ + CD_ * 32 + CD_))] = 0.f;
    }
}

// ---------------- K1: z_e via f32x2 timestep pairs (R7-proven) ----------------
__global__ void __launch_bounds__(512) ze_kernel(const float* __restrict__ z)
{
    __shared__ u64 s_part[16][32][CD_];    // 32 KB

    const int tid  = threadIdx.x;
    const int w    = tid >> 5;
    const int lane = tid & 31;
    const int tb   = blockIdx.x * 64;
    const int b    = tb >> 12;
    const int tt   = (tb & (T_ - 1)) + 2 * lane;

    const float* zp = z + ((size_t)b * DIM_ + w * 64) * T_ + tt;
    const float* wp = g_Win2 + (w * 64) * 16;

    u64 acc[CD_];
#pragma unroll
    for (int c = 0; c < CD_; ++c) acc[c] = 0ull;    // (0.0f, 0.0f)

#pragma unroll 8
    for (int d = 0; d < 64; ++d) {
        u64 zv = *(const u64*)(zp + (size_t)d * T_);             // 2 timesteps, coalesced
        const ulonglong2* wr = (const ulonglong2*)(wp + d * 16); // warp-uniform splat
        ulonglong2 w0 = wr[0], w1 = wr[1], w2 = wr[2], w3 = wr[3];
        acc[0] = f2fma(zv, w0.x, acc[0]);
        acc[1] = f2fma(zv, w0.y, acc[1]);
        acc[2] = f2fma(zv, w1.x, acc[2]);
        acc[3] = f2fma(zv, w1.y, acc[3]);
        acc[4] = f2fma(zv, w2.x, acc[4]);
        acc[5] = f2fma(zv, w2.y, acc[5]);
        acc[6] = f2fma(zv, w3.x, acc[6]);
        acc[7] = f2fma(zv, w3.y, acc[7]);
    }
#pragma unroll
    for (int c = 0; c < CD_; ++c) s_part[w][lane][c] = acc[c];
    __syncthreads();

    if (tid < 256) {
        const int tp = tid >> 3, c = tid & 7;
        u64 s = *(const u64*)(g_bin2 + 2 * c);
#pragma unroll
        for (int k = 0; k < 16; ++k) s = f2add(s, s_part[k][tp][c]);
        float2 f = f2unpack(s);
        g_ze[(size_t)(tb + 2 * tp) * CD_ + c]     = f.x;
        g_ze[(size_t)(tb + 2 * tp + 1) * CD_ + c] = f.y;
    }
}

// ---------------- K2: search + finalize + out-proj, fused ----------------
// 512 threads, 64 timesteps per block. Phase geometries identical to the
// R7-proven split kernels; q-tile passes through smem instead of global.
// 2 blocks/SM so one block's DRAM-store phase overlaps the other's fma phase.
__global__ void __launch_bounds__(512, 2) sfo_kernel(const float* __restrict__ codebook,
                                                     float* __restrict__ dout)
{
    __shared__ float s_bv[NSL_][64];
    __shared__ int   s_bi[NSL_][64];
    __shared__ int   s_idx[64];
    __shared__ float s_red[512];
    __shared__ float s_q[32 * 16];        // pair-interleaved codes [pair][c][2], 2 KB

    const int tid  = threadIdx.x;
    const int w    = tid >> 5;            // warp 0..15 (= slice in search, row-chunk in outproj)
    const int lane = tid & 31;
    const int tb   = blockIdx.x * 64;     // block's first timestep (within one batch)
    const int b    = tb >> 12;
    const int tl   = tb & (T_ - 1);

    // ---- phase 1: search (R7 geometry, bit-identical dot chains) ----
    {
        const ulonglong2* zp0 = (const ulonglong2*)(g_ze + (size_t)(tb + lane) * CD_);
        const ulonglong2* zp1 = (const ulonglong2*)(g_ze + (size_t)(tb + 32 + lane) * CD_);
        ulonglong2 zA = zp0[0], zB = zp0[1];   // t0
        ulonglong2 zC = zp1[0], zD = zp1[1];   // t1

        float best0 = -3.4e38f, best1 = -3.4e38f;
        int i0 = 0, i1 = 0;

        const ulonglong2* cr = (const ulonglong2*)g_cn + (size_t)w * SLICE_ * 2;
#pragma unroll 2
        for (int j = 0; j < SLICE_; ++j) {
            ulonglong2 k0 = cr[2 * j], k1 = cr[2 * j + 1];   // warp-uniform, L1 broadcast

            u64 dA = f2mul(zA.x, k0.x);
            dA = f2fma(zA.y, k0.y, dA);
            dA = f2fma(zB.x, k1.x, dA);
            dA = f2fma(zB.y, k1.y, dA);
            u64 dB = f2mul(zC.x, k0.x);
            dB = f2fma(zC.y, k0.y, dB);
            dB = f2fma(zD.x, k1.x, dB);
            dB = f2fma(zD.y, k1.y, dB);

            float2 fa = f2unpack(dA);
            float2 fb = f2unpack(dB);
            float dot0 = fa.x + fa.y;
            float dot1 = fb.x + fb.y;
            if (dot0 > best0) { best0 = dot0; i0 = j; }      // strict > : lowest j on tie
            if (dot1 > best1) { best1 = dot1; i1 = j; }
        }

        s_bv[w][lane]      = best0;  s_bi[w][lane]      = i0 + w * SLICE_;
        s_bv[w][lane + 32] = best1;  s_bi[w][lane + 32] = i1 + w * SLICE_;
    }
    __syncthreads();

    // ---- phase 2: merge across 16 slices (ascending keeps lowest global j on ties) ----
    if (tid < 64) {
        float bv = s_bv[0][tid]; int bi = s_bi[0][tid];
#pragma unroll
        for (int s = 1; s < NSL_; ++s) {
            float ov = s_bv[s][tid];
            if (ov > bv) { bv = ov; bi = s_bi[s][tid]; }
        }
        s_idx[tid] = bi;
        dout[IDX_OFF_ + tb + tid] = (float)bi;               // exactly representable
    }
    __syncthreads();

    // ---- phase 3: finalize — gather codes into smem q-tile, loss reduce ----
    {
        const int t = tid >> 3, c = tid & 7;                 // t 0..63, c 0..7
        const int idx = s_idx[t];
        float qv = __ldg(codebook + (size_t)idx * CD_ + c);
        float ev = g_ze[(size_t)(tb + t) * CD_ + c];
        float d_ = ev - qv;
        s_red[tid] = d_ * d_;
        s_q[(t >> 1) * 16 + 2 * c + (t & 1)] = qv;           // pair-interleaved
    }
    __syncthreads();
#pragma unroll
    for (int s = 256; s > 0; s >>= 1) {
        if (tid < s) s_red[tid] += s_red[tid + s];
        __syncthreads();
    }
    if (tid == 0)
        atomicAdd(&dout[LOSS_OFF_ + b], s_red[0] * (1.25f / 32768.f));
    __syncthreads();

    // ---- phase 4: out-proj. Warp w -> rows [w*64, w*64+64); lane = pair ----
    {
        const u64* qs = (const u64*)(s_q + lane * 16);       // this lane's pair
        u64 q0 = qs[0], q1 = qs[1], q2 = qs[2], q3 = qs[3];
        u64 q4 = qs[4], q5 = qs[5], q6 = qs[6], q7 = qs[7];

        float* outp = dout + ((size_t)b * DIM_ + w * 64) * T_ + tl + 2 * lane;
        const float* wbase = g_Wout2 + (w * 64) * 16;
        const float* bbase = g_bout2 + (w * 64) * 2;

#pragma unroll 4
        for (int r = 0; r < 64; ++r) {
            const ulonglong2* wr = (const ulonglong2*)(wbase + r * 16);  // warp-uniform, L1
            ulonglong2 w0 = wr[0], w1 = wr[1], w2 = wr[2], w3 = wr[3];
            u64 acc = *(const u64*)(bbase + r * 2);
            acc = f2fma(w0.x, q0, acc);
            acc = f2fma(w0.y, q1, acc);
            acc = f2fma(w1.x, q2, acc);
            acc = f2fma(w1.y, q3, acc);
            acc = f2fma(w2.x, q4, acc);
            acc = f2fma(w2.y, q5, acc);
            acc = f2fma(w3.x, q6, acc);
            acc = f2fma(w3.y, q7, acc);
            *(u64*)(outp + (size_t)r * T_) = acc;            // float2 store, 256B/warp
        }
    }
}

// ---------------- launcher ----------------
extern "C" void kernel_launch(void* const* d_in, const int* in_sizes, int n_in,
                              void* d_out, int out_size)
{
    const float* z        = (const float*)d_in[0];
    const float* v_in     = (const float*)d_in[1];
    const float* g_in     = (const float*)d_in[2];
    const float* b_in     = (const float*)d_in[3];
    const float* codebook = (const float*)d_in[4];
    const float* v_out    = (const float*)d_in[5];
    const float* g_out    = (const float*)d_in[6];
    const float* b_out    = (const float*)d_in[7];
    float* out = (float*)d_out;

    prep_kernel<<<22, 256>>>(v_in, g_in, b_in, codebook, v_out, g_out, b_out, out);
    ze_kernel<<<BT_ / 64, 512>>>(z);
    sfo_kernel<<<BT_ / 64, 512>>>(codebook, out);
}

// round 9
// speedup vs baseline: 1.0891x; 1.0891x over previous
#include <cuda_runtime.h>

typedef unsigned long long u64;

#define B_    8
#define DIM_  1024
#define T_    4096
#define CB_   4096
#define CD_   8
#define BT_   (B_*T_)
#define NSL_  16
#define SLICE_ (CB_/NSL_)   // 256

static const size_t IDX_OFF_  = (size_t)B_ * DIM_ * T_;          // 33554432
static const size_t LOSS_OFF_ = (size_t)B_ * DIM_ * T_ + BT_;    // 33587200

// ---------------- device scratch (no allocations allowed) ----------------
__device__ float g_cn[CB_ * CD_];          // normalized codebook [j][c] (128 KB, L1-resident)
__device__ float g_Win2[DIM_ * 2 * CD_];   // weight-normed in_proj, transposed+splatted [d][c][2]
__device__ float g_bin2[2 * CD_];          // b_in splatted [c][2]
__device__ float g_Wout2[DIM_ * 2 * CD_];  // weight-normed out_proj, splatted [o][c][2]
__device__ float g_bout2[DIM_ * 2];        // b_out splatted [o][2]
__device__ float g_ze[(size_t)BT_ * CD_];  // encodings z_e [t][c]  (1 MB)
__device__ float g_qp[(size_t)BT_ * CD_];  // gathered codes, pair-interleaved [tp][c][2]

// ---------------- f32x2 helpers ----------------
__device__ __forceinline__ u64 f2mul(u64 a, u64 b) {
    u64 r; asm("mul.rn.f32x2 %0, %1, %2;" : "=l"(r) : "l"(a), "l"(b)); return r;
}
__device__ __forceinline__ u64 f2fma(u64 a, u64 b, u64 c) {
    u64 r; asm("fma.rn.f32x2 %0, %1, %2, %3;" : "=l"(r) : "l"(a), "l"(b), "l"(c)); return r;
}
__device__ __forceinline__ u64 f2add(u64 a, u64 b) {
    u64 r; asm("add.rn.f32x2 %0, %1, %2;" : "=l"(r) : "l"(a), "l"(b)); return r;
}
__device__ __forceinline__ float2 f2unpack(u64 a) {
    float x, y; asm("mov.b64 {%0, %1}, %2;" : "=f"(x), "=f"(y) : "l"(a));
    return make_float2(x, y);
}

// ---------------- prep v2: 8 threads/row + shfl group reduce, 162 blocks ----------------
__global__ void __launch_bounds__(256) prep_kernel(
    const float* __restrict__ v_in, const float* __restrict__ g_in,
    const float* __restrict__ b_in,
    const float* __restrict__ codebook,
    const float* __restrict__ v_out, const float* __restrict__ g_out,
    const float* __restrict__ b_out, float* __restrict__ dout)
{
    const int r = blockIdx.x * 256 + threadIdx.x;

    if (r < CB_ * 8) {
        // A: codebook norm. 8 threads/row, fully coalesced.
        const int row = r >> 3, c = r & 7;
        float v = codebook[(size_t)row * CD_ + c];
        float s = v * v;
        s += __shfl_xor_sync(0xffffffffu, s, 1);
        s += __shfl_xor_sync(0xffffffffu, s, 2);
        s += __shfl_xor_sync(0xffffffffu, s, 4);
        float n = fmaxf(sqrtf(s), 1e-12f);
        g_cn[(size_t)row * CD_ + c] = v / n;
    } else if (r < CB_ * 8 + DIM_ * 8) {
        // B: out_proj weight-norm + splat. 8 threads/row.
        const int idx = r - CB_ * 8;
        const int o = idx >> 3, c = idx & 7;
        float v = v_out[(size_t)o * CD_ + c];
        float s = v * v;
        s += __shfl_xor_sync(0xffffffffu, s, 1);
        s += __shfl_xor_sync(0xffffffffu, s, 2);
        s += __shfl_xor_sync(0xffffffffu, s, 4);
        float w = v * (g_out[o] / sqrtf(s));
        g_Wout2[o * 16 + 2 * c]     = w;
        g_Wout2[o * 16 + 2 * c + 1] = w;
        if (c == 0) {
            float bb = b_out[o];
            g_bout2[o * 2] = bb; g_bout2[o * 2 + 1] = bb;
        }
    } else if (r < CB_ * 8 + DIM_ * 8 + CD_ * 32) {
        // C: in_proj — one warp per output channel; transposed+splatted W_in
        const int idx  = r - (CB_ * 8 + DIM_ * 8);
        const int w    = idx >> 5;
        const int lane = idx & 31;
        float s = 0.f;
        for (int d = lane; d < DIM_; d += 32) {
            float v = v_in[(size_t)w * DIM_ + d]; s += v * v;
        }
#pragma unroll
        for (int off = 16; off > 0; off >>= 1) s += __shfl_xor_sync(0xffffffffu, s, off);
        float sc = g_in[w] / sqrtf(s);
        for (int d = lane; d < DIM_; d += 32) {
            float val = v_in[(size_t)w * DIM_ + d] * sc;
            g_Win2[d * 16 + 2 * w]     = val;
            g_Win2[d * 16 + 2 * w + 1] = val;
        }
    } else if (r < CB_ * 8 + DIM_ * 8 + CD_ * 32 + CD_) {
        // D: b_in splat
        const int c = r - (CB_ * 8 + DIM_ * 8 + CD_ * 32);
        float bv = b_in[c];
        g_bin2[2 * c] = bv; g_bin2[2 * c + 1] = bv;
    } else if (r < CB_ * 8 + DIM_ * 8 + CD_ * 32 + CD_ + B_) {
        // E: zero loss accumulators (graph-replay safe)
        dout[LOSS_OFF_ + (r - (CB_ * 8 + DIM_ * 8 + CD_ * 32 + CD_))] = 0.f;
    }
}

// ---------------- K1: z_e via f32x2 timestep pairs (R7-proven, unchanged) ----------------
__global__ void __launch_bounds__(512) ze_kernel(const float* __restrict__ z)
{
    __shared__ u64 s_part[16][32][CD_];    // 32 KB

    const int tid  = threadIdx.x;
    const int w    = tid >> 5;
    const int lane = tid & 31;
    const int tb   = blockIdx.x * 64;
    const int b    = tb >> 12;
    const int tt   = (tb & (T_ - 1)) + 2 * lane;

    const float* zp = z + ((size_t)b * DIM_ + w * 64) * T_ + tt;
    const float* wp = g_Win2 + (w * 64) * 16;

    u64 acc[CD_];
#pragma unroll
    for (int c = 0; c < CD_; ++c) acc[c] = 0ull;    // (0.0f, 0.0f)

#pragma unroll 8
    for (int d = 0; d < 64; ++d) {
        u64 zv = *(const u64*)(zp + (size_t)d * T_);             // 2 timesteps, coalesced
        const ulonglong2* wr = (const ulonglong2*)(wp + d * 16); // warp-uniform splat
        ulonglong2 w0 = wr[0], w1 = wr[1], w2 = wr[2], w3 = wr[3];
        acc[0] = f2fma(zv, w0.x, acc[0]);
        acc[1] = f2fma(zv, w0.y, acc[1]);
        acc[2] = f2fma(zv, w1.x, acc[2]);
        acc[3] = f2fma(zv, w1.y, acc[3]);
        acc[4] = f2fma(zv, w2.x, acc[4]);
        acc[5] = f2fma(zv, w2.y, acc[5]);
        acc[6] = f2fma(zv, w3.x, acc[6]);
        acc[7] = f2fma(zv, w3.y, acc[7]);
    }
#pragma unroll
    for (int c = 0; c < CD_; ++c) s_part[w][lane][c] = acc[c];
    __syncthreads();

    if (tid < 256) {
        const int tp = tid >> 3, c = tid & 7;
        u64 s = *(const u64*)(g_bin2 + 2 * c);
#pragma unroll
        for (int k = 0; k < 16; ++k) s = f2add(s, s_part[k][tp][c]);
        float2 f = f2unpack(s);
        g_ze[(size_t)(tb + 2 * tp) * CD_ + c]     = f.x;
        g_ze[(size_t)(tb + 2 * tp + 1) * CD_ + c] = f.y;
    }
}

// ---------------- K2: search + finalize fused (R7-proven, unchanged) ----------------
__global__ void __launch_bounds__(512, 2) search_kernel(const float* __restrict__ codebook,
                                                        float* __restrict__ dout)
{
    __shared__ float s_bv[NSL_][64];
    __shared__ int   s_bi[NSL_][64];
    __shared__ int   s_idx[64];
    __shared__ float s_red[512];

    const int tid  = threadIdx.x;
    const int w    = tid >> 5;             // slice 0..15
    const int lane = tid & 31;
    const int tb   = blockIdx.x * 64;
    const int b    = tb >> 12;

    const ulonglong2* zp0 = (const ulonglong2*)(g_ze + (size_t)(tb + lane) * CD_);
    const ulonglong2* zp1 = (const ulonglong2*)(g_ze + (size_t)(tb + 32 + lane) * CD_);
    ulonglong2 zA = zp0[0], zB = zp0[1];   // t0
    ulonglong2 zC = zp1[0], zD = zp1[1];   // t1

    float best0 = -3.4e38f, best1 = -3.4e38f;
    int i0 = 0, i1 = 0;

    const ulonglong2* cr = (const ulonglong2*)g_cn + (size_t)w * SLICE_ * 2;
#pragma unroll 2
    for (int j = 0; j < SLICE_; ++j) {
        ulonglong2 k0 = cr[2 * j], k1 = cr[2 * j + 1];   // warp-uniform, L1 broadcast

        u64 dA = f2mul(zA.x, k0.x);
        dA = f2fma(zA.y, k0.y, dA);
        dA = f2fma(zB.x, k1.x, dA);
        dA = f2fma(zB.y, k1.y, dA);
        u64 dB = f2mul(zC.x, k0.x);
        dB = f2fma(zC.y, k0.y, dB);
        dB = f2fma(zD.x, k1.x, dB);
        dB = f2fma(zD.y, k1.y, dB);

        float2 fa = f2unpack(dA);
        float2 fb = f2unpack(dB);
        float dot0 = fa.x + fa.y;
        float dot1 = fb.x + fb.y;
        if (dot0 > best0) { best0 = dot0; i0 = j; }      // strict > : lowest j on tie
        if (dot1 > best1) { best1 = dot1; i1 = j; }
    }

    s_bv[w][lane]      = best0;  s_bi[w][lane]      = i0 + w * SLICE_;
    s_bv[w][lane + 32] = best1;  s_bi[w][lane + 32] = i1 + w * SLICE_;
    __syncthreads();

    if (tid < 64) {
        float bv = s_bv[0][tid]; int bi = s_bi[0][tid];
#pragma unroll
        for (int s = 1; s < NSL_; ++s) {
            float ov = s_bv[s][tid];
            if (ov > bv) { bv = ov; bi = s_bi[s][tid]; }  // ascending s keeps lowest j
        }
        s_idx[tid] = bi;
        dout[IDX_OFF_ + tb + tid] = (float)bi;
    }
    __syncthreads();

    {
        const int t = tid >> 3, c = tid & 7;
        const int idx = s_idx[t];
        float qv = __ldg(codebook + (size_t)idx * CD_ + c);
        float ev = g_ze[(size_t)(tb + t) * CD_ + c];
        float d_ = ev - qv;
        s_red[tid] = d_ * d_;
        g_qp[(size_t)((tb + t) >> 1) * 16 + 2 * c + (t & 1)] = qv;
    }
    __syncthreads();
#pragma unroll
    for (int s = 256; s > 0; s >>= 1) {
        if (tid < s) s_red[tid] += s_red[tid + s];
        __syncthreads();
    }
    if (tid == 0)
        atomicAdd(&dout[LOSS_OFF_ + b], s_red[0] * (1.25f / 32768.f));
}

// ---------------- K3: out-proj v3 — 2 pairs/thread, STG.128, transposed q-tile ----------------
// Block = 256 threads; covers 64 o-rows x 128 t-pairs (= 256 timesteps).
// s_qT is TRANSPOSED [c2][pair] so per-thread q loads are conflict-free LDS.128.
__global__ void __launch_bounds__(256) outproj_kernel(float* __restrict__ dout)
{
    __shared__ float s_w[64 * 16];     // splatted weights, 4 KB
    __shared__ float s_b[64 * 2];      // splatted bias
    __shared__ float s_qT[16 * 128];   // q tile transposed [c2 u64][pair], 8 KB

    const int tid = threadIdx.x;
    const int oc  = blockIdx.x & 15;          // o-row chunk 0..15
    const int pc  = blockIdx.x >> 4;          // pair chunk 0..127

    // stage weights + bias (coalesced)
    ((float4*)s_w)[tid] = ((const float4*)(g_Wout2 + oc * 64 * 16))[tid];
    if (tid < 32) ((float4*)s_b)[tid] = ((const float4*)(g_bout2 + oc * 64 * 2))[tid];

    // stage q transposed: read g_qp coalesced float4, scatter as u64 into [c2][pair]
    {
        u64* qt = (u64*)s_qT;
        const float4* src = (const float4*)(g_qp + (size_t)pc * 128 * 16);
#pragma unroll
        for (int k = 0; k < 2; ++k) {
            const int idx = tid + k * 256;           // 512 float4 = 128 pairs x 4 quads
            float4 f = src[idx];
            const int p = idx >> 2, qd = idx & 3;    // pair, quad (u64s 2qd, 2qd+1)
            u64 lo, hi;
            asm("mov.b64 %0, {%1, %2};" : "=l"(lo) : "f"(f.x), "f"(f.y));
            asm("mov.b64 %0, {%1, %2};" : "=l"(hi) : "f"(f.z), "f"(f.w));
            qt[(2 * qd)     * 128 + p] = lo;
            qt[(2 * qd + 1) * 128 + p] = hi;
        }
    }
    __syncthreads();

    const int dp = tid & 63;          // double-pair 0..63 (owns pairs 2dp, 2dp+1)
    const int qu = tid >> 6;          // row quarter 0..3 (16 rows each)

    // q for both pairs: 16 u64, conflict-free LDS.128 (lane-contiguous 16B chunks)
    u64 p0, p1, p2, p3, p4, p5, p6, p7;   // pair 2dp
    u64 r0, r1, r2, r3, r4, r5, r6, r7;   // pair 2dp+1
    {
        const ulonglong2* qt = (const ulonglong2*)s_qT;
        ulonglong2 v0 = qt[(0 * 128 + 2 * dp) >> 1 + 0];  // placeholder (replaced below)
        (void)v0;
        const u64* q64 = (const u64*)s_qT;
#pragma unroll
        for (int c2 = 0; c2 < 8; ++c2) {
            ulonglong2 v = *(const ulonglong2*)(q64 + c2 * 128 + 2 * dp);
            switch (c2) {
                case 0: p0 = v.x; r0 = v.y; break;
                case 1: p1 = v.x; r1 = v.y; break;
                case 2: p2 = v.x; r2 = v.y; break;
                case 3: p3 = v.x; r3 = v.y; break;
                case 4: p4 = v.x; r4 = v.y; break;
                case 5: p5 = v.x; r5 = v.y; break;
                case 6: p6 = v.x; r6 = v.y; break;
                case 7: p7 = v.x; r7 = v.y; break;
            }
        }
    }

    const int t0 = (pc * 128 + 2 * dp) * 2;   // first of 4 contiguous timesteps
    const int b  = t0 >> 12;
    const int tl = t0 & (T_ - 1);
    float* outp = dout + ((size_t)b * DIM_ + oc * 64 + qu * 16) * T_ + tl;

#pragma unroll 4
    for (int i = 0; i < 16; ++i) {
        const ulonglong2* wr = (const ulonglong2*)(s_w + (qu * 16 + i) * 16);  // uniform LDS
        ulonglong2 w0 = wr[0], w1 = wr[1], w2 = wr[2], w3 = wr[3];
        u64 bb = *(const u64*)(s_b + (qu * 16 + i) * 2);
        u64 a0 = bb, a1 = bb;
        a0 = f2fma(w0.x, p0, a0);  a1 = f2fma(w0.x, r0, a1);
        a0 = f2fma(w0.y, p1, a0);  a1 = f2fma(w0.y, r1, a1);
        a0 = f2fma(w1.x, p2, a0);  a1 = f2fma(w1.x, r2, a1);
        a0 = f2fma(w1.y, p3, a0);  a1 = f2fma(w1.y, r3, a1);
        a0 = f2fma(w2.x, p4, a0);  a1 = f2fma(w2.x, r4, a1);
        a0 = f2fma(w2.y, p5, a0);  a1 = f2fma(w2.y, r5, a1);
        a0 = f2fma(w3.x, p6, a0);  a1 = f2fma(w3.x, r6, a1);
        a0 = f2fma(w3.y, p7, a0);  a1 = f2fma(w3.y, r7, a1);
        ulonglong2 st; st.x = a0; st.y = a1;
        *(ulonglong2*)(outp + (size_t)i * T_) = st;   // STG.128, 512B/warp coalesced
    }
}

// ---------------- launcher ----------------
extern "C" void kernel_launch(void* const* d_in, const int* in_sizes, int n_in,
                              void* d_out, int out_size)
{
    const float* z        = (const float*)d_in[0];
    const float* v_in     = (const float*)d_in[1];
    const float* g_in     = (const float*)d_in[2];
    const float* b_in     = (const float*)d_in[3];
    const float* codebook = (const float*)d_in[4];
    const float* v_out    = (const float*)d_in[5];
    const float* g_out    = (const float*)d_in[6];
    const float* b_out    = (const float*)d_in[7];
    float* out = (float*)d_out;

    prep_kernel<<<162, 256>>>(v_in, g_in, b_in, codebook, v_out, g_out, b_out, out);
    ze_kernel<<<BT_ / 64, 512>>>(z);
    search_kernel<<<BT_ / 64, 512>>>(codebook, out);
    outproj_kernel<<<2048, 256>>>(out);
}

// round 10
// speedup vs baseline: 1.2120x; 1.1128x over previous
#include <cuda_runtime.h>

typedef unsigned long long u64;

#define B_    8
#define DIM_  1024
#define T_    4096
#define CB_   4096
#define CD_   8
#define BT_   (B_*T_)
#define NSL_  16
#define SLICE_ (CB_/NSL_)   // 256
#define HALF_T_ (BT_/2)     // 16384 timesteps per pipeline chunk

static const size_t IDX_OFF_  = (size_t)B_ * DIM_ * T_;          // 33554432
static const size_t LOSS_OFF_ = (size_t)B_ * DIM_ * T_ + BT_;    // 33587200

// ---------------- device scratch (no allocations allowed) ----------------
__device__ float g_cn[CB_ * CD_];          // normalized codebook [j][c] (128 KB, L1-resident)
__device__ float g_Win2[DIM_ * 2 * CD_];   // weight-normed in_proj, transposed+splatted [d][c][2]
__device__ float g_bin2[2 * CD_];          // b_in splatted [c][2]
__device__ float g_Wout2[DIM_ * 2 * CD_];  // weight-normed out_proj, splatted [o][c][2]
__device__ float g_bout2[DIM_ * 2];        // b_out splatted [o][2]
__device__ float g_ze[(size_t)BT_ * CD_];  // encodings z_e [t][c]  (1 MB)
__device__ float g_qp[(size_t)BT_ * CD_];  // gathered codes, pair-interleaved [tp][c][2]

// ---------------- f32x2 helpers ----------------
__device__ __forceinline__ u64 f2mul(u64 a, u64 b) {
    u64 r; asm("mul.rn.f32x2 %0, %1, %2;" : "=l"(r) : "l"(a), "l"(b)); return r;
}
__device__ __forceinline__ u64 f2fma(u64 a, u64 b, u64 c) {
    u64 r; asm("fma.rn.f32x2 %0, %1, %2, %3;" : "=l"(r) : "l"(a), "l"(b), "l"(c)); return r;
}
__device__ __forceinline__ u64 f2add(u64 a, u64 b) {
    u64 r; asm("add.rn.f32x2 %0, %1, %2;" : "=l"(r) : "l"(a), "l"(b)); return r;
}
__device__ __forceinline__ float2 f2unpack(u64 a) {
    float x, y; asm("mov.b64 {%0, %1}, %2;" : "=f"(x), "=f"(y) : "l"(a));
    return make_float2(x, y);
}

// ---------------- prep v2: 8 threads/row + shfl group reduce ----------------
__global__ void __launch_bounds__(256) prep_kernel(
    const float* __restrict__ v_in, const float* __restrict__ g_in,
    const float* __restrict__ b_in,
    const float* __restrict__ codebook,
    const float* __restrict__ v_out, const float* __restrict__ g_out,
    const float* __restrict__ b_out, float* __restrict__ dout)
{
    const int r = blockIdx.x * 256 + threadIdx.x;

    if (r < CB_ * 8) {
        const int row = r >> 3, c = r & 7;
        float v = codebook[(size_t)row * CD_ + c];
        float s = v * v;
        s += __shfl_xor_sync(0xffffffffu, s, 1);
        s += __shfl_xor_sync(0xffffffffu, s, 2);
        s += __shfl_xor_sync(0xffffffffu, s, 4);
        float n = fmaxf(sqrtf(s), 1e-12f);
        g_cn[(size_t)row * CD_ + c] = v / n;
    } else if (r < CB_ * 8 + DIM_ * 8) {
        const int idx = r - CB_ * 8;
        const int o = idx >> 3, c = idx & 7;
        float v = v_out[(size_t)o * CD_ + c];
        float s = v * v;
        s += __shfl_xor_sync(0xffffffffu, s, 1);
        s += __shfl_xor_sync(0xffffffffu, s, 2);
        s += __shfl_xor_sync(0xffffffffu, s, 4);
        float w = v * (g_out[o] / sqrtf(s));
        g_Wout2[o * 16 + 2 * c]     = w;
        g_Wout2[o * 16 + 2 * c + 1] = w;
        if (c == 0) {
            float bb = b_out[o];
            g_bout2[o * 2] = bb; g_bout2[o * 2 + 1] = bb;
        }
    } else if (r < CB_ * 8 + DIM_ * 8 + CD_ * 32) {
        const int idx  = r - (CB_ * 8 + DIM_ * 8);
        const int w    = idx >> 5;
        const int lane = idx & 31;
        float s = 0.f;
        for (int d = lane; d < DIM_; d += 32) {
            float v = v_in[(size_t)w * DIM_ + d]; s += v * v;
        }
#pragma unroll
        for (int off = 16; off > 0; off >>= 1) s += __shfl_xor_sync(0xffffffffu, s, off);
        float sc = g_in[w] / sqrtf(s);
        for (int d = lane; d < DIM_; d += 32) {
            float val = v_in[(size_t)w * DIM_ + d] * sc;
            g_Win2[d * 16 + 2 * w]     = val;
            g_Win2[d * 16 + 2 * w + 1] = val;
        }
    } else if (r < CB_ * 8 + DIM_ * 8 + CD_ * 32 + CD_) {
        const int c = r - (CB_ * 8 + DIM_ * 8 + CD_ * 32);
        float bv = b_in[c];
        g_bin2[2 * c] = bv; g_bin2[2 * c + 1] = bv;
    } else if (r < CB_ * 8 + DIM_ * 8 + CD_ * 32 + CD_ + B_) {
        dout[LOSS_OFF_ + (r - (CB_ * 8 + DIM_ * 8 + CD_ * 32 + CD_))] = 0.f;
    }
}

// ---------------- K1: z_e via f32x2 timestep pairs (R7-proven; +tofs) ----------------
__global__ void __launch_bounds__(512) ze_kernel(const float* __restrict__ z, int tofs)
{
    __shared__ u64 s_part[16][32][CD_];    // 32 KB

    const int tid  = threadIdx.x;
    const int w    = tid >> 5;
    const int lane = tid & 31;
    const int tb   = tofs + blockIdx.x * 64;
    const int b    = tb >> 12;
    const int tt   = (tb & (T_ - 1)) + 2 * lane;

    const float* zp = z + ((size_t)b * DIM_ + w * 64) * T_ + tt;
    const float* wp = g_Win2 + (w * 64) * 16;

    u64 acc[CD_];
#pragma unroll
    for (int c = 0; c < CD_; ++c) acc[c] = 0ull;    // (0.0f, 0.0f)

#pragma unroll 8
    for (int d = 0; d < 64; ++d) {
        u64 zv = *(const u64*)(zp + (size_t)d * T_);             // 2 timesteps, coalesced
        const ulonglong2* wr = (const ulonglong2*)(wp + d * 16); // warp-uniform splat
        ulonglong2 w0 = wr[0], w1 = wr[1], w2 = wr[2], w3 = wr[3];
        acc[0] = f2fma(zv, w0.x, acc[0]);
        acc[1] = f2fma(zv, w0.y, acc[1]);
        acc[2] = f2fma(zv, w1.x, acc[2]);
        acc[3] = f2fma(zv, w1.y, acc[3]);
        acc[4] = f2fma(zv, w2.x, acc[4]);
        acc[5] = f2fma(zv, w2.y, acc[5]);
        acc[6] = f2fma(zv, w3.x, acc[6]);
        acc[7] = f2fma(zv, w3.y, acc[7]);
    }
#pragma unroll
    for (int c = 0; c < CD_; ++c) s_part[w][lane][c] = acc[c];
    __syncthreads();

    if (tid < 256) {
        const int tp = tid >> 3, c = tid & 7;
        u64 s = *(const u64*)(g_bin2 + 2 * c);
#pragma unroll
        for (int k = 0; k < 16; ++k) s = f2add(s, s_part[k][tp][c]);
        float2 f = f2unpack(s);
        g_ze[(size_t)(tb + 2 * tp) * CD_ + c]     = f.x;
        g_ze[(size_t)(tb + 2 * tp + 1) * CD_ + c] = f.y;
    }
}

// ---------------- K2: search + finalize fused (R7-proven; +tofs) ----------------
__global__ void __launch_bounds__(512, 2) search_kernel(const float* __restrict__ codebook,
                                                        float* __restrict__ dout, int tofs)
{
    __shared__ float s_bv[NSL_][64];
    __shared__ int   s_bi[NSL_][64];
    __shared__ int   s_idx[64];
    __shared__ float s_red[512];

    const int tid  = threadIdx.x;
    const int w    = tid >> 5;             // slice 0..15
    const int lane = tid & 31;
    const int tb   = tofs + blockIdx.x * 64;
    const int b    = tb >> 12;

    const ulonglong2* zp0 = (const ulonglong2*)(g_ze + (size_t)(tb + lane) * CD_);
    const ulonglong2* zp1 = (const ulonglong2*)(g_ze + (size_t)(tb + 32 + lane) * CD_);
    ulonglong2 zA = zp0[0], zB = zp0[1];   // t0
    ulonglong2 zC = zp1[0], zD = zp1[1];   // t1

    float best0 = -3.4e38f, best1 = -3.4e38f;
    int i0 = 0, i1 = 0;

    const ulonglong2* cr = (const ulonglong2*)g_cn + (size_t)w * SLICE_ * 2;
#pragma unroll 2
    for (int j = 0; j < SLICE_; ++j) {
        ulonglong2 k0 = cr[2 * j], k1 = cr[2 * j + 1];   // warp-uniform, L1 broadcast

        u64 dA = f2mul(zA.x, k0.x);
        dA = f2fma(zA.y, k0.y, dA);
        dA = f2fma(zB.x, k1.x, dA);
        dA = f2fma(zB.y, k1.y, dA);
        u64 dB = f2mul(zC.x, k0.x);
        dB = f2fma(zC.y, k0.y, dB);
        dB = f2fma(zD.x, k1.x, dB);
        dB = f2fma(zD.y, k1.y, dB);

        float2 fa = f2unpack(dA);
        float2 fb = f2unpack(dB);
        float dot0 = fa.x + fa.y;
        float dot1 = fb.x + fb.y;
        if (dot0 > best0) { best0 = dot0; i0 = j; }      // strict > : lowest j on tie
        if (dot1 > best1) { best1 = dot1; i1 = j; }
    }

    s_bv[w][lane]      = best0;  s_bi[w][lane]      = i0 + w * SLICE_;
    s_bv[w][lane + 32] = best1;  s_bi[w][lane + 32] = i1 + w * SLICE_;
    __syncthreads();

    if (tid < 64) {
        float bv = s_bv[0][tid]; int bi = s_bi[0][tid];
#pragma unroll
        for (int s = 1; s < NSL_; ++s) {
            float ov = s_bv[s][tid];
            if (ov > bv) { bv = ov; bi = s_bi[s][tid]; }  // ascending s keeps lowest j
        }
        s_idx[tid] = bi;
        dout[IDX_OFF_ + tb + tid] = (float)bi;
    }
    __syncthreads();

    {
        const int t = tid >> 3, c = tid & 7;
        const int idx = s_idx[t];
        float qv = __ldg(codebook + (size_t)idx * CD_ + c);
        float ev = g_ze[(size_t)(tb + t) * CD_ + c];
        float d_ = ev - qv;
        s_red[tid] = d_ * d_;
        g_qp[(size_t)((tb + t) >> 1) * 16 + 2 * c + (t & 1)] = qv;
    }
    __syncthreads();
#pragma unroll
    for (int s = 256; s > 0; s >>= 1) {
        if (tid < s) s_red[tid] += s_red[tid + s];
        __syncthreads();
    }
    if (tid == 0)
        atomicAdd(&dout[LOSS_OFF_ + b], s_red[0] * (1.25f / 32768.f));
}

// ---------------- K3: out-proj v3 (R9-proven; +pofs) ----------------
// Block = 256 threads; covers 64 o-rows x 128 t-pairs (= 256 timesteps).
__global__ void __launch_bounds__(256) outproj_kernel(float* __restrict__ dout, int pofs)
{
    __shared__ float s_w[64 * 16];     // splatted weights, 4 KB
    __shared__ float s_b[64 * 2];      // splatted bias
    __shared__ float s_qT[16 * 128];   // q tile transposed [c2 u64][pair], 8 KB

    const int tid = threadIdx.x;
    const int oc  = blockIdx.x & 15;          // o-row chunk 0..15
    const int pc  = (blockIdx.x >> 4) + pofs; // pair chunk

    // stage weights + bias (coalesced)
    ((float4*)s_w)[tid] = ((const float4*)(g_Wout2 + oc * 64 * 16))[tid];
    if (tid < 32) ((float4*)s_b)[tid] = ((const float4*)(g_bout2 + oc * 64 * 2))[tid];

    // stage q transposed: read g_qp coalesced float4, scatter as u64 into [c2][pair]
    {
        u64* qt = (u64*)s_qT;
        const float4* src = (const float4*)(g_qp + (size_t)pc * 128 * 16);
#pragma unroll
        for (int k = 0; k < 2; ++k) {
            const int idx = tid + k * 256;           // 512 float4 = 128 pairs x 4 quads
            float4 f = src[idx];
            const int p = idx >> 2, qd = idx & 3;    // pair, quad (u64s 2qd, 2qd+1)
            u64 lo, hi;
            asm("mov.b64 %0, {%1, %2};" : "=l"(lo) : "f"(f.x), "f"(f.y));
            asm("mov.b64 %0, {%1, %2};" : "=l"(hi) : "f"(f.z), "f"(f.w));
            qt[(2 * qd)     * 128 + p] = lo;
            qt[(2 * qd + 1) * 128 + p] = hi;
        }
    }
    __syncthreads();

    const int dp = tid & 63;          // double-pair 0..63 (owns pairs 2dp, 2dp+1)
    const int qu = tid >> 6;          // row quarter 0..3 (16 rows each)

    // q for both pairs: 16 u64, conflict-free LDS.128 (lane-contiguous 16B chunks)
    u64 p0, p1, p2, p3, p4, p5, p6, p7;   // pair 2dp
    u64 r0, r1, r2, r3, r4, r5, r6, r7;   // pair 2dp+1
    {
        const u64* q64 = (const u64*)s_qT;
        ulonglong2 v;
        v = *(const ulonglong2*)(q64 + 0 * 128 + 2 * dp); p0 = v.x; r0 = v.y;
        v = *(const ulonglong2*)(q64 + 1 * 128 + 2 * dp); p1 = v.x; r1 = v.y;
        v = *(const ulonglong2*)(q64 + 2 * 128 + 2 * dp); p2 = v.x; r2 = v.y;
        v = *(const ulonglong2*)(q64 + 3 * 128 + 2 * dp); p3 = v.x; r3 = v.y;
        v = *(const ulonglong2*)(q64 + 4 * 128 + 2 * dp); p4 = v.x; r4 = v.y;
        v = *(const ulonglong2*)(q64 + 5 * 128 + 2 * dp); p5 = v.x; r5 = v.y;
        v = *(const ulonglong2*)(q64 + 6 * 128 + 2 * dp); p6 = v.x; r6 = v.y;
        v = *(const ulonglong2*)(q64 + 7 * 128 + 2 * dp); p7 = v.x; r7 = v.y;
    }

    const int t0 = (pc * 128 + 2 * dp) * 2;   // first of 4 contiguous timesteps
    const int b  = t0 >> 12;
    const int tl = t0 & (T_ - 1);
    float* outp = dout + ((size_t)b * DIM_ + oc * 64 + qu * 16) * T_ + tl;

#pragma unroll 4
    for (int i = 0; i < 16; ++i) {
        const ulonglong2* wr = (const ulonglong2*)(s_w + (qu * 16 + i) * 16);  // uniform LDS
        ulonglong2 w0 = wr[0], w1 = wr[1], w2 = wr[2], w3 = wr[3];
        u64 bb = *(const u64*)(s_b + (qu * 16 + i) * 2);
        u64 a0 = bb, a1 = bb;
        a0 = f2fma(w0.x, p0, a0);  a1 = f2fma(w0.x, r0, a1);
        a0 = f2fma(w0.y, p1, a0);  a1 = f2fma(w0.y, r1, a1);
        a0 = f2fma(w1.x, p2, a0);  a1 = f2fma(w1.x, r2, a1);
        a0 = f2fma(w1.y, p3, a0);  a1 = f2fma(w1.y, r3, a1);
        a0 = f2fma(w2.x, p4, a0);  a1 = f2fma(w2.x, r4, a1);
        a0 = f2fma(w2.y, p5, a0);  a1 = f2fma(w2.y, r5, a1);
        a0 = f2fma(w3.x, p6, a0);  a1 = f2fma(w3.x, r6, a1);
        a0 = f2fma(w3.y, p7, a0);  a1 = f2fma(w3.y, r7, a1);
        ulonglong2 st; st.x = a0; st.y = a1;
        *(ulonglong2*)(outp + (size_t)i * T_) = st;   // STG.128, 512B/warp coalesced
    }
}

// ---------------- launcher: 2-stream software pipeline ----------------
// d : prep -> ze_A -> search_A -> outproj_A
// s1:            \-> ze_B -> search_B -> outproj_B
// search_A (fma) overlaps ze_B (DRAM read); outproj_A (DRAM write) overlaps
// search_B (fma). Streams/events created once (host-side; no device allocs);
// identical work every call -> deterministic and graph-capturable.
extern "C" void kernel_launch(void* const* d_in, const int* in_sizes, int n_in,
                              void* d_out, int out_size)
{
    const float* z        = (const float*)d_in[0];
    const float* v_in     = (const float*)d_in[1];
    const float* g_in     = (const float*)d_in[2];
    const float* b_in     = (const float*)d_in[3];
    const float* codebook = (const float*)d_in[4];
    const float* v_out    = (const float*)d_in[5];
    const float* g_out    = (const float*)d_in[6];
    const float* b_out    = (const float*)d_in[7];
    float* out = (float*)d_out;

    static cudaStream_t s1 = nullptr;
    static cudaEvent_t  eFork = nullptr, eJoin = nullptr;
    if (s1 == nullptr) {
        cudaStreamCreateWithFlags(&s1, cudaStreamNonBlocking);
        cudaEventCreateWithFlags(&eFork, cudaEventDisableTiming);
        cudaEventCreateWithFlags(&eJoin, cudaEventDisableTiming);
    }

    prep_kernel<<<162, 256>>>(v_in, g_in, b_in, codebook, v_out, g_out, b_out, out);
    ze_kernel<<<HALF_T_ / 64, 512>>>(z, 0);

    cudaEventRecord(eFork, 0);                 // fork after ze_A (prep also done)
    cudaStreamWaitEvent(s1, eFork, 0);

    ze_kernel<<<HALF_T_ / 64, 512, 0, s1>>>(z, HALF_T_);

    search_kernel<<<HALF_T_ / 64, 512>>>(codebook, out, 0);
    outproj_kernel<<<1024, 256>>>(out, 0);

    search_kernel<<<HALF_T_ / 64, 512, 0, s1>>>(codebook, out, HALF_T_);
    outproj_kernel<<<1024, 256, 0, s1>>>(out, 64);

    cudaEventRecord(eJoin, s1);                // join
    cudaStreamWaitEvent(0, eJoin, 0);
}